// round 4
// baseline (speedup 1.0000x reference)
#include <cuda_runtime.h>
#include <cuda_bf16.h>

#define SEQ    2048
#define BATCH  64
#define D      256
#define HSIZE  4096
#define HMASK  (HSIZE - 1)

#define GCHUNKS 8
#define GCHUNK_S (SEQ / GCHUNKS)     // 256
#define HALVES  2                    // 128 dims each

#define H1 100
#define H2 150

#define MLP_CTAS 128                 // <= 148 -> guaranteed single wave

// Scratch (device globals — no allocations allowed)
__device__ float g_w    [BATCH * SEQ];             // tf*idf weights, transposed
__device__ int   g_tokT [BATCH * SEQ];             // tokens, transposed
__device__ float g_partial[BATCH * GCHUNKS * D];   // per-chunk pooled partials
__device__ float g_pooled [BATCH * D];
__device__ float g_h1     [BATCH * H1];
__device__ float g_h2     [BATCH * H2];
__device__ int   g_bar_count;                      // zero-init; returns to 0
__device__ int   g_bar_sense;                      // flips; read fresh each run

__device__ __forceinline__ unsigned hash_tok(int tok) {
    return ((unsigned)tok * 2654435761u) & HMASK;
}

// ---------------------------------------------------------------------------
// Kernel 1: per-batch histogram -> weights + transposed tokens.
// ---------------------------------------------------------------------------
__global__ __launch_bounds__(256)
void weight_kernel(const int* __restrict__ x, const float* __restrict__ idf) {
    __shared__ int tok_sh[SEQ];     // 8 KB
    __shared__ int hkey[HSIZE];     // 16 KB
    __shared__ int hcnt[HSIZE];     // 16 KB

    const int tid = threadIdx.x;
    const int b   = blockIdx.x;

    #pragma unroll
    for (int i = tid; i < HSIZE; i += 256) { hkey[i] = -1; hcnt[i] = 0; }
    #pragma unroll
    for (int s = tid; s < SEQ; s += 256) tok_sh[s] = x[s * BATCH + b];
    __syncthreads();

    #pragma unroll
    for (int s = tid; s < SEQ; s += 256) {
        int tok = tok_sh[s];
        if (tok == 0) continue;
        unsigned h = hash_tok(tok);
        while (true) {
            int prev = atomicCAS(&hkey[h], -1, tok);
            if (prev == -1 || prev == tok) { atomicAdd(&hcnt[h], 1); break; }
            h = (h + 1) & HMASK;
        }
    }
    __syncthreads();

    #pragma unroll
    for (int s = tid; s < SEQ; s += 256) {
        int tok = tok_sh[s];
        float w = 0.0f;
        if (tok != 0) {
            unsigned h = hash_tok(tok);
            while (hkey[h] != tok) h = (h + 1) & HMASK;
            w = (float)hcnt[h] * __ldg(&idf[tok]);
        }
        g_w   [b * SEQ + s] = w;
        g_tokT[b * SEQ + s] = tok;
    }
}

// ---------------------------------------------------------------------------
// Kernel 2: gather. grid = BATCH * HALVES * GCHUNKS = 1024 CTAs, tiny smem.
// CTA (b, half, chunk): 8 warps, warp w covers 32 seq positions; each lane
// accumulates one float4 (4 dims) of the 128-dim half.
// ---------------------------------------------------------------------------
__global__ __launch_bounds__(256)
void gather_kernel(const float* __restrict__ emb) {
    __shared__ int    tok_s[GCHUNK_S];   // 1 KB
    __shared__ float  w_s  [GCHUNK_S];   // 1 KB
    __shared__ float4 red[8][32];        // 4 KB

    const int tid  = threadIdx.x;
    const int lane = tid & 31;
    const int wrp  = tid >> 5;

    const int b     = blockIdx.x >> 4;
    const int half  = (blockIdx.x >> 3) & 1;
    const int chunk = blockIdx.x & 7;

    const int sbase = chunk * GCHUNK_S;
    // preload tokens + weights for this chunk (coalesced)
    for (int i = tid; i < GCHUNK_S; i += 256) {
        tok_s[i] = __ldcg(&g_tokT[b * SEQ + sbase + i]);
        w_s[i]   = __ldcg(&g_w   [b * SEQ + sbase + i]);
    }
    __syncthreads();

    const float4* emb4 = reinterpret_cast<const float4*>(emb);
    const int doff = half * 32 + lane;   // float4 index within a row

    float4 acc = make_float4(0.f, 0.f, 0.f, 0.f);
    const int s0 = wrp * 32;
    #pragma unroll 4
    for (int i = 0; i < 32; i++) {
        int   tok = tok_s[s0 + i];
        float wv  = w_s  [s0 + i];
        float4 v  = __ldg(emb4 + (size_t)tok * (D / 4) + doff);
        acc.x += wv * v.x;
        acc.y += wv * v.y;
        acc.z += wv * v.z;
        acc.w += wv * v.w;
    }
    red[wrp][lane] = acc;
    __syncthreads();

    if (tid < 32) {
        float4 r = red[0][tid];
        #pragma unroll
        for (int w = 1; w < 8; w++) {
            float4 a = red[w][tid];
            r.x += a.x; r.y += a.y; r.z += a.z; r.w += a.w;
        }
        float4* dst = reinterpret_cast<float4*>(
            g_partial + ((size_t)b * GCHUNKS + chunk) * D + half * 128);
        dst[tid] = r;
    }
}

// ---------------------------------------------------------------------------
// Kernel 3: whole MLP in one launch; grid-wide sense-reversing spin barrier
// between layers. 128 CTAs x 256 threads = 1024 warps, warp-per-output tasks.
// ---------------------------------------------------------------------------
__device__ __forceinline__ void grid_barrier(int& sense) {
    __syncthreads();
    if (threadIdx.x == 0) {
        __threadfence();
        int t = atomicAdd(&g_bar_count, 1);
        sense ^= 1;
        if (t == MLP_CTAS - 1) {
            g_bar_count = 0;
            __threadfence();
            atomicExch(&g_bar_sense, sense);
        } else {
            while (atomicAdd(&g_bar_sense, 0) != sense) { }
        }
    }
    __syncthreads();
}

__global__ __launch_bounds__(256)
void mlp_kernel(const float* __restrict__ W1, const float* __restrict__ b1,
                const float* __restrict__ W2, const float* __restrict__ b2,
                const float* __restrict__ W3, const float* __restrict__ b3,
                float* __restrict__ out) {
    const int tid  = threadIdx.x;
    const int lane = tid & 31;
    const int wrp  = tid >> 5;
    const int gw   = blockIdx.x * 8 + wrp;   // global warp id, 0..1023

    int sense = 0;
    if (tid == 0) sense = atomicAdd(&g_bar_sense, 0);

    // stage 0: reduce chunk partials -> pooled. CTAs 0..63, one per batch.
    if (blockIdx.x < BATCH) {
        const int b = blockIdx.x;
        const float* p = g_partial + (size_t)b * GCHUNKS * D;
        float s = 0.f;
        #pragma unroll
        for (int c = 0; c < GCHUNKS; c++) s += __ldcg(p + c * D + tid);
        g_pooled[b * D + tid] = s;
    }
    grid_barrier(sense);

    // L1: 6400 tasks (b, j), dot over 256.
    for (int t = gw; t < BATCH * H1; t += MLP_CTAS * 8) {
        const int b = t / H1, j = t % H1;
        const float* P = g_pooled + (size_t)b * D;
        const float* W = W1 + (size_t)j * D;
        float s = 0.f;
        #pragma unroll
        for (int d = lane; d < D; d += 32) s += __ldcg(P + d) * __ldg(W + d);
        #pragma unroll
        for (int o = 16; o; o >>= 1) s += __shfl_xor_sync(0xffffffffu, s, o);
        if (lane == 0) g_h1[b * H1 + j] = fmaxf(s + __ldg(b1 + j), 0.f);
    }
    grid_barrier(sense);

    // L2: 9600 tasks (b, j), dot over 100.
    for (int t = gw; t < BATCH * H2; t += MLP_CTAS * 8) {
        const int b = t / H2, j = t % H2;
        const float* Hv = g_h1 + (size_t)b * H1;
        const float* W  = W2 + (size_t)j * H1;
        float s = 0.f;
        for (int d = lane; d < H1; d += 32) s += __ldcg(Hv + d) * __ldg(W + d);
        #pragma unroll
        for (int o = 16; o; o >>= 1) s += __shfl_xor_sync(0xffffffffu, s, o);
        if (lane == 0) g_h2[b * H2 + j] = fmaxf(s + __ldg(b2 + j), 0.f);
    }
    grid_barrier(sense);

    // L3 + softmax: warp per batch (first 64 warps).
    if (gw < BATCH) {
        const int b = gw;
        const float* Hv = g_h2 + (size_t)b * H2;
        float s0 = 0.f, s1 = 0.f;
        for (int d = lane; d < H2; d += 32) {
            float h = __ldcg(Hv + d);
            s0 += h * __ldg(W3 + d);
            s1 += h * __ldg(W3 + H2 + d);
        }
        #pragma unroll
        for (int o = 16; o; o >>= 1) {
            s0 += __shfl_xor_sync(0xffffffffu, s0, o);
            s1 += __shfl_xor_sync(0xffffffffu, s1, o);
        }
        if (lane == 0) {
            float z0 = s0 + __ldg(b3), z1 = s1 + __ldg(b3 + 1);
            float m  = fmaxf(z0, z1);
            float e0 = expf(z0 - m);
            float e1 = expf(z1 - m);
            float inv = 1.0f / (e0 + e1);
            out[b * 2 + 0] = e0 * inv;
            out[b * 2 + 1] = e1 * inv;
        }
    }
}

extern "C" void kernel_launch(void* const* d_in, const int* in_sizes, int n_in,
                              void* d_out, int out_size) {
    const int*   x   = (const int*)  d_in[0];
    const float* emb = (const float*)d_in[1];
    const float* idf = (const float*)d_in[2];
    const float* W1  = (const float*)d_in[3];
    const float* b1  = (const float*)d_in[4];
    const float* W2  = (const float*)d_in[5];
    const float* b2  = (const float*)d_in[6];
    const float* W3  = (const float*)d_in[7];
    const float* b3  = (const float*)d_in[8];
    float* out = (float*)d_out;

    weight_kernel<<<BATCH, 256>>>(x, idf);
    gather_kernel<<<BATCH * HALVES * GCHUNKS, 256>>>(emb);
    mlp_kernel<<<MLP_CTAS, 256>>>(W1, b1, W2, b2, W3, b3, out);
}

// round 5
// speedup vs baseline: 1.2572x; 1.2572x over previous
#include <cuda_runtime.h>
#include <cuda_bf16.h>

#define SEQ    2048
#define BATCH  64
#define D      256
#define CHUNKS 4
#define CHUNK_S (SEQ / CHUNKS)   // 512
#define HSIZE  4096
#define HMASK  (HSIZE - 1)
#define PT     512               // pool threads per CTA

#define H1 100
#define H2 150
#define MLP_CTAS 128             // <= 148 -> guaranteed co-resident

// Scratch (device globals — no allocations allowed)
__device__ float g_partial[BATCH * CHUNKS * D];
__device__ float g_pooled [BATCH * D];
__device__ float g_h1     [BATCH * H1];
__device__ float g_h2     [BATCH * H2];
__device__ int   g_bar_count;    // zero-init; returns to 0 each barrier
__device__ int   g_bar_sense;    // flips; read fresh at kernel start

__device__ __forceinline__ unsigned hash_tok(int tok) {
    return ((unsigned)tok * 2654435761u) & HMASK;
}

// ---------------------------------------------------------------------------
// Kernel 1: per (batch, seq-chunk) CTA, 512 threads.
// Full-row histogram in smem (redundant across the 4 chunk-CTAs — proven
// cheaper than any low-CTA-count alternative), then weighted embedding
// gather for this chunk.
// ---------------------------------------------------------------------------
__global__ __launch_bounds__(PT, 2)
void pool_kernel(const int* __restrict__ x,
                 const float* __restrict__ emb,
                 const float* __restrict__ idf) {
    __shared__ int    tok_sh[SEQ];      // 8 KB
    __shared__ int    hkey[HSIZE];      // 16 KB
    __shared__ int    hcnt[HSIZE];      // 16 KB
    __shared__ float  w_sh[CHUNK_S];    // 2 KB
    __shared__ float4 red4[8][D / 4];   // 8 KB

    const int tid   = threadIdx.x;
    const int b     = blockIdx.x >> 2;
    const int chunk = blockIdx.x & 3;

    #pragma unroll
    for (int i = tid; i < HSIZE; i += PT) { hkey[i] = -1; hcnt[i] = 0; }
    #pragma unroll
    for (int s = tid; s < SEQ; s += PT) tok_sh[s] = x[s * BATCH + b];
    __syncthreads();

    #pragma unroll
    for (int s = tid; s < SEQ; s += PT) {
        int tok = tok_sh[s];
        if (tok == 0) continue;
        unsigned h = hash_tok(tok);
        while (true) {
            int prev = atomicCAS(&hkey[h], -1, tok);
            if (prev == -1 || prev == tok) { atomicAdd(&hcnt[h], 1); break; }
            h = (h + 1) & HMASK;
        }
    }
    __syncthreads();

    const int base = chunk * CHUNK_S;
    {
        int i = tid;                          // CHUNK_S == PT
        int tok = tok_sh[base + i];
        float w = 0.0f;
        if (tok != 0) {
            unsigned h = hash_tok(tok);
            while (hkey[h] != tok) h = (h + 1) & HMASK;
            w = (float)hcnt[h] * __ldg(&idf[tok]);
        }
        w_sh[i] = w;
    }
    __syncthreads();

    // gather: sg in [0,8) picks s ≡ sg (mod 8); dq in [0,64) picks float4 dim
    const int sg = tid >> 6;
    const int dq = tid & 63;

    float4 acc = make_float4(0.f, 0.f, 0.f, 0.f);
    #pragma unroll 4
    for (int s = sg; s < CHUNK_S; s += 8) {
        float w  = w_sh[s];
        int  tok = tok_sh[base + s];
        float4 v = __ldg(reinterpret_cast<const float4*>(emb) + (size_t)tok * (D / 4) + dq);
        acc.x += w * v.x;
        acc.y += w * v.y;
        acc.z += w * v.z;
        acc.w += w * v.w;
    }
    red4[sg][dq] = acc;
    __syncthreads();

    if (tid < D / 4) {
        float4 r = red4[0][tid];
        #pragma unroll
        for (int k = 1; k < 8; k++) {
            float4 a = red4[k][tid];
            r.x += a.x; r.y += a.y; r.z += a.z; r.w += a.w;
        }
        reinterpret_cast<float4*>(g_partial + ((size_t)b * CHUNKS + chunk) * D)[tid] = r;
    }
}

// ---------------------------------------------------------------------------
// Kernel 2: whole MLP in one launch with grid-wide sense-reversing barrier.
// 128 CTAs x 256 threads = 1024 warps; warp-per-output tasks each layer.
// ---------------------------------------------------------------------------
__device__ __forceinline__ void grid_barrier(int& sense) {
    __syncthreads();
    if (threadIdx.x == 0) {
        __threadfence();
        int t = atomicAdd(&g_bar_count, 1);
        sense ^= 1;
        if (t == MLP_CTAS - 1) {
            g_bar_count = 0;
            __threadfence();
            atomicExch(&g_bar_sense, sense);
        } else {
            while (atomicAdd(&g_bar_sense, 0) != sense) { }
        }
    }
    __syncthreads();
}

__global__ __launch_bounds__(256)
void mlp_kernel(const float* __restrict__ W1, const float* __restrict__ b1,
                const float* __restrict__ W2, const float* __restrict__ b2,
                const float* __restrict__ W3, const float* __restrict__ b3,
                float* __restrict__ out) {
    const int tid  = threadIdx.x;
    const int lane = tid & 31;
    const int wrp  = tid >> 5;
    const int gw   = blockIdx.x * 8 + wrp;   // global warp id, 0..1023

    int sense = 0;
    if (tid == 0) sense = atomicAdd(&g_bar_sense, 0);

    // stage 0: reduce the 4 chunk partials -> pooled (CTAs 0..63).
    if (blockIdx.x < BATCH) {
        const int b = blockIdx.x;
        const float* p = g_partial + (size_t)b * CHUNKS * D;
        float s = 0.f;
        #pragma unroll
        for (int c = 0; c < CHUNKS; c++) s += __ldcg(p + c * D + tid);
        g_pooled[b * D + tid] = s;
    }
    grid_barrier(sense);

    // L1: 6400 tasks (b, j), dot over 256.
    for (int t = gw; t < BATCH * H1; t += MLP_CTAS * 8) {
        const int b = t / H1, j = t % H1;
        const float* P = g_pooled + (size_t)b * D;
        const float* W = W1 + (size_t)j * D;
        float s = 0.f;
        #pragma unroll
        for (int d = lane; d < D; d += 32) s += __ldcg(P + d) * __ldg(W + d);
        #pragma unroll
        for (int o = 16; o; o >>= 1) s += __shfl_xor_sync(0xffffffffu, s, o);
        if (lane == 0) g_h1[b * H1 + j] = fmaxf(s + __ldg(b1 + j), 0.f);
    }
    grid_barrier(sense);

    // L2: 9600 tasks (b, j), dot over 100.
    for (int t = gw; t < BATCH * H2; t += MLP_CTAS * 8) {
        const int b = t / H2, j = t % H2;
        const float* Hv = g_h1 + (size_t)b * H1;
        const float* W  = W2 + (size_t)j * H1;
        float s = 0.f;
        for (int d = lane; d < H1; d += 32) s += __ldcg(Hv + d) * __ldg(W + d);
        #pragma unroll
        for (int o = 16; o; o >>= 1) s += __shfl_xor_sync(0xffffffffu, s, o);
        if (lane == 0) g_h2[b * H2 + j] = fmaxf(s + __ldg(b2 + j), 0.f);
    }
    grid_barrier(sense);

    // L3 + softmax: warp per batch (first 64 warps).
    if (gw < BATCH) {
        const int b = gw;
        const float* Hv = g_h2 + (size_t)b * H2;
        float s0 = 0.f, s1 = 0.f;
        for (int d = lane; d < H2; d += 32) {
            float h = __ldcg(Hv + d);
            s0 += h * __ldg(W3 + d);
            s1 += h * __ldg(W3 + H2 + d);
        }
        #pragma unroll
        for (int o = 16; o; o >>= 1) {
            s0 += __shfl_xor_sync(0xffffffffu, s0, o);
            s1 += __shfl_xor_sync(0xffffffffu, s1, o);
        }
        if (lane == 0) {
            float z0 = s0 + __ldg(b3), z1 = s1 + __ldg(b3 + 1);
            float m  = fmaxf(z0, z1);
            float e0 = expf(z0 - m);
            float e1 = expf(z1 - m);
            float inv = 1.0f / (e0 + e1);
            out[b * 2 + 0] = e0 * inv;
            out[b * 2 + 1] = e1 * inv;
        }
    }
}

extern "C" void kernel_launch(void* const* d_in, const int* in_sizes, int n_in,
                              void* d_out, int out_size) {
    const int*   x   = (const int*)  d_in[0];
    const float* emb = (const float*)d_in[1];
    const float* idf = (const float*)d_in[2];
    const float* W1  = (const float*)d_in[3];
    const float* b1  = (const float*)d_in[4];
    const float* W2  = (const float*)d_in[5];
    const float* b2  = (const float*)d_in[6];
    const float* W3  = (const float*)d_in[7];
    const float* b3  = (const float*)d_in[8];
    float* out = (float*)d_out;

    pool_kernel<<<BATCH * CHUNKS, PT>>>(x, emb, idf);
    mlp_kernel<<<MLP_CTAS, 256>>>(W1, b1, W2, b2, W3, b3, out);
}

// round 8
// speedup vs baseline: 1.5589x; 1.2400x over previous
#include <cuda_runtime.h>
#include <cuda_bf16.h>

#define SEQ    2048
#define BATCH  64
#define D      256
#define CHUNKS 4
#define CHUNK_S (SEQ / CHUNKS)   // 512
#define HSIZE  4096
#define HMASK  (HSIZE - 1)
#define NT     256

#define H1 100
#define H2 150

// smem float layout for mlp kernel (all offsets float4-aligned)
#define W1_STRIDE 257                      // (j + d) % 32 -> conflict-free
#define W2_STRIDE 101                      // gcd(5,32)=1  -> conflict-free
#define OFF_W1   0
#define OFF_W2   (OFF_W1 + H1 * W1_STRIDE)         // 25700
#define OFF_W3   (OFF_W2 + 15152)                   // W2 padded to 16B mult
#define OFF_PL   (OFF_W3 + 300)
#define OFF_H1   (OFF_PL + D)
#define OFF_H2   (OFF_H1 + 104)
#define MLP_SMEM_FLOATS (OFF_H2 + 152)
#define MLP_SMEM_BYTES  (MLP_SMEM_FLOATS * 4)       // ~167 KB

// Scratch (device globals — no allocations allowed)
__device__ float g_partial[BATCH * CHUNKS * D];

__device__ __forceinline__ unsigned hash_tok(int tok) {
    return ((unsigned)tok * 2654435761u) & HMASK;
}

// ---------------------------------------------------------------------------
// Kernel 1: per (batch, seq-chunk) CTA — TF-IDF weighted embedding gather.
// R2-proven structure; gather loop now runs TWO independent accumulator
// streams to double memory-level parallelism on the DRAM-bound emb reads.
// ---------------------------------------------------------------------------
__global__ __launch_bounds__(NT, 2)
void pool_kernel(const int* __restrict__ x,
                 const float* __restrict__ emb,
                 const float* __restrict__ idf) {
    __shared__ int    tok_sh[SEQ];      // 8 KB
    __shared__ int    hkey[HSIZE];      // 16 KB
    __shared__ int    hcnt[HSIZE];      // 16 KB
    __shared__ float  w_sh[CHUNK_S];    // 2 KB
    __shared__ float4 red4[4][D / 4];   // 4 KB

    const int tid   = threadIdx.x;
    const int b     = blockIdx.x >> 2;
    const int chunk = blockIdx.x & 3;

    #pragma unroll
    for (int i = tid; i < HSIZE; i += NT) { hkey[i] = -1; hcnt[i] = 0; }
    #pragma unroll
    for (int s = tid; s < SEQ; s += NT) tok_sh[s] = x[s * BATCH + b];
    __syncthreads();

    #pragma unroll
    for (int s = tid; s < SEQ; s += NT) {
        int tok = tok_sh[s];
        if (tok == 0) continue;
        unsigned h = hash_tok(tok);
        while (true) {
            int prev = atomicCAS(&hkey[h], -1, tok);
            if (prev == -1 || prev == tok) { atomicAdd(&hcnt[h], 1); break; }
            h = (h + 1) & HMASK;
        }
    }
    __syncthreads();

    const int base = chunk * CHUNK_S;
    for (int i = tid; i < CHUNK_S; i += NT) {
        int tok = tok_sh[base + i];
        float w = 0.0f;
        if (tok != 0) {
            unsigned h = hash_tok(tok);
            while (hkey[h] != tok) h = (h + 1) & HMASK;
            w = (float)hcnt[h] * __ldg(&idf[tok]);
        }
        w_sh[i] = w;
    }
    __syncthreads();

    // gather: sg in [0,4) picks s ≡ sg (mod 4); dq in [0,64) picks float4 dim.
    // Two independent streams: [0, 256) and [256, 512).
    const int sg = tid >> 6;
    const int dq = tid & 63;
    const float4* emb4 = reinterpret_cast<const float4*>(emb);

    float4 acc0 = make_float4(0.f, 0.f, 0.f, 0.f);
    float4 acc1 = make_float4(0.f, 0.f, 0.f, 0.f);
    #pragma unroll 4
    for (int s = sg; s < CHUNK_S / 2; s += 4) {
        int   tokA = tok_sh[base + s];
        int   tokB = tok_sh[base + s + CHUNK_S / 2];
        float wA   = w_sh[s];
        float wB   = w_sh[s + CHUNK_S / 2];
        float4 vA  = __ldg(emb4 + (size_t)tokA * (D / 4) + dq);
        float4 vB  = __ldg(emb4 + (size_t)tokB * (D / 4) + dq);
        acc0.x += wA * vA.x;  acc0.y += wA * vA.y;
        acc0.z += wA * vA.z;  acc0.w += wA * vA.w;
        acc1.x += wB * vB.x;  acc1.y += wB * vB.y;
        acc1.z += wB * vB.z;  acc1.w += wB * vB.w;
    }
    acc0.x += acc1.x; acc0.y += acc1.y; acc0.z += acc1.z; acc0.w += acc1.w;
    red4[sg][dq] = acc0;
    __syncthreads();

    if (tid < D / 4) {
        float4 a = red4[0][tid];
        float4 c = red4[1][tid];
        float4 e = red4[2][tid];
        float4 f = red4[3][tid];
        float4 r = make_float4(a.x + c.x + e.x + f.x,
                               a.y + c.y + e.y + f.y,
                               a.z + c.z + e.z + f.z,
                               a.w + c.w + e.w + f.w);
        reinterpret_cast<float4*>(g_partial + ((size_t)b * CHUNKS + chunk) * D)[tid] = r;
    }
}

// ---------------------------------------------------------------------------
// Kernel 2: per-batch MLP, one CTA per batch (64 CTAs, 256 threads), no grid
// sync. All weights staged into dynamic smem with conflict-free padded
// layouts; compute is thread-per-output reading smem.
// ---------------------------------------------------------------------------
__global__ __launch_bounds__(256)
void mlp_kernel(const float* __restrict__ W1, const float* __restrict__ b1,
                const float* __restrict__ W2, const float* __restrict__ b2,
                const float* __restrict__ W3, const float* __restrict__ b3,
                float* __restrict__ out) {
    extern __shared__ float sm[];
    float* w1s = sm + OFF_W1;
    float* w2s = sm + OFF_W2;
    float* w3s = sm + OFF_W3;
    float* pls = sm + OFF_PL;
    float* h1s = sm + OFF_H1;
    float* h2s = sm + OFF_H2;

    const int tid = threadIdx.x;
    const int b   = blockIdx.x;

    // reduce the 4 chunk partials -> pooled (issue first; overlaps staging)
    {
        const float* p = g_partial + (size_t)b * CHUNKS * D;
        float s = __ldcg(p + tid) + __ldcg(p + D + tid) +
                  __ldcg(p + 2 * D + tid) + __ldcg(p + 3 * D + tid);
        pls[tid] = s;
    }

    // stage W1 [100 x 256] -> w1s row stride 257 (coalesced f4 reads)
    const float4* W1v = reinterpret_cast<const float4*>(W1);
    for (int f = tid; f < H1 * (D / 4); f += 256) {
        int j  = f >> 6;          // / 64
        int dq = f & 63;
        float4 v = __ldg(W1v + f);
        float* dst = w1s + j * W1_STRIDE + dq * 4;
        dst[0] = v.x; dst[1] = v.y; dst[2] = v.z; dst[3] = v.w;
    }
    // stage W2 [150 x 100] -> w2s row stride 101
    const float4* W2v = reinterpret_cast<const float4*>(W2);
    for (int f = tid; f < H2 * (H1 / 4); f += 256) {
        int j  = f / 25;
        int dq = f % 25;
        float4 v = __ldg(W2v + f);
        float* dst = w2s + j * W2_STRIDE + dq * 4;
        dst[0] = v.x; dst[1] = v.y; dst[2] = v.z; dst[3] = v.w;
    }
    // stage W3 [2 x 150] flat
    const float4* W3v = reinterpret_cast<const float4*>(W3);
    if (tid < 75) {
        float4 v = __ldg(W3v + tid);
        float* dst = w3s + tid * 4;
        dst[0] = v.x; dst[1] = v.y; dst[2] = v.z; dst[3] = v.w;
    }
    __syncthreads();

    // L1: thread j (j<100): h1[j] = relu(dot(pooled, W1[j,:]) + b1[j])
    if (tid < H1) {
        const float* w = w1s + tid * W1_STRIDE;
        float a0 = 0.f, a1 = 0.f, a2 = 0.f, a3 = 0.f;
        #pragma unroll 8
        for (int d = 0; d < D; d += 4) {
            a0 += pls[d + 0] * w[d + 0];
            a1 += pls[d + 1] * w[d + 1];
            a2 += pls[d + 2] * w[d + 2];
            a3 += pls[d + 3] * w[d + 3];
        }
        h1s[tid] = fmaxf((a0 + a1) + (a2 + a3) + __ldg(b1 + tid), 0.f);
    }
    __syncthreads();

    // L2: thread j (j<150): h2[j] = relu(dot(h1, W2[j,:]) + b2[j])
    if (tid < H2) {
        const float* w = w2s + tid * W2_STRIDE;
        float a0 = 0.f, a1 = 0.f, a2 = 0.f, a3 = 0.f;
        #pragma unroll 5
        for (int d = 0; d < H1; d += 4) {
            a0 += h1s[d + 0] * w[d + 0];
            a1 += h1s[d + 1] * w[d + 1];
            a2 += h1s[d + 2] * w[d + 2];
            a3 += h1s[d + 3] * w[d + 3];
        }
        h2s[tid] = fmaxf((a0 + a1) + (a2 + a3) + __ldg(b2 + tid), 0.f);
    }
    __syncthreads();

    // L3 + softmax: trivial tail, one thread.
    if (tid == 0) {
        float z0 = 0.f, z1 = 0.f;
        #pragma unroll 5
        for (int d = 0; d < H2; d++) {
            float h = h2s[d];
            z0 += h * w3s[d];
            z1 += h * w3s[H2 + d];
        }
        z0 += __ldg(b3);
        z1 += __ldg(b3 + 1);
        float m  = fmaxf(z0, z1);
        float e0 = expf(z0 - m);
        float e1 = expf(z1 - m);
        float inv = 1.0f / (e0 + e1);
        out[b * 2 + 0] = e0 * inv;
        out[b * 2 + 1] = e1 * inv;
    }
}

extern "C" void kernel_launch(void* const* d_in, const int* in_sizes, int n_in,
                              void* d_out, int out_size) {
    const int*   x   = (const int*)  d_in[0];
    const float* emb = (const float*)d_in[1];
    const float* idf = (const float*)d_in[2];
    const float* W1  = (const float*)d_in[3];
    const float* b1  = (const float*)d_in[4];
    const float* W2  = (const float*)d_in[5];
    const float* b2  = (const float*)d_in[6];
    const float* W3  = (const float*)d_in[7];
    const float* b3  = (const float*)d_in[8];
    float* out = (float*)d_out;

    static int smem_set = 0;
    if (!smem_set) {
        cudaFuncSetAttribute(mlp_kernel,
                             cudaFuncAttributeMaxDynamicSharedMemorySize,
                             MLP_SMEM_BYTES);
        smem_set = 1;
    }

    pool_kernel<<<BATCH * CHUNKS, NT>>>(x, emb, idf);
    mlp_kernel<<<BATCH, 256, MLP_SMEM_BYTES>>>(W1, b1, W2, b2, W3, b3, out);
}

// round 10
// speedup vs baseline: 1.6459x; 1.0558x over previous
#include <cuda_runtime.h>
#include <cuda_bf16.h>

#define SEQ    2048
#define BATCH  64
#define D      256
#define CHUNKS 4
#define CHUNK_S (SEQ / CHUNKS)   // 512
#define HSIZE  4096
#define HMASK  (HSIZE - 1)
#define NT     256

#define H1 100
#define H2 150
#define MT 1024                            // MLP threads per CTA

// smem float layout for mlp kernel
#define W1_STRIDE 257
#define W2_STRIDE 101
#define OFF_W1   0
#define OFF_W2   (OFF_W1 + H1 * W1_STRIDE)          // 25700
#define OFF_W3   (OFF_W2 + H2 * W2_STRIDE + 2)      // 40852
#define OFF_PL   (OFF_W3 + 300)                     // 41152
#define OFF_H1   (OFF_PL + D)                       // 41408
#define OFF_H2   (OFF_H1 + 104)                     // 41512
#define OFF_B1   (OFF_H2 + 152)                     // 41664
#define OFF_B2   (OFF_B1 + 104)                     // 41768
#define OFF_B3   (OFF_B2 + 152)                     // 41920
#define OFF_Z    (OFF_B3 + 4)                       // 41924
#define MLP_SMEM_FLOATS (OFF_Z + 8)
#define MLP_SMEM_BYTES  (MLP_SMEM_FLOATS * 4)       // ~167.7 KB

// Scratch (device globals — no allocations allowed)
__device__ float g_partial[BATCH * CHUNKS * D];

__device__ __forceinline__ unsigned hash_tok(int tok) {
    return ((unsigned)tok * 2654435761u) & HMASK;
}

// ---------------------------------------------------------------------------
// Kernel 1: per (batch, seq-chunk) CTA — TF-IDF weighted embedding gather.
// (unchanged — passing, near L2 floor)
// ---------------------------------------------------------------------------
__global__ __launch_bounds__(NT, 2)
void pool_kernel(const int* __restrict__ x,
                 const float* __restrict__ emb,
                 const float* __restrict__ idf) {
    __shared__ int    tok_sh[SEQ];
    __shared__ int    hkey[HSIZE];
    __shared__ int    hcnt[HSIZE];
    __shared__ float  w_sh[CHUNK_S];
    __shared__ float4 red4[4][D / 4];

    const int tid   = threadIdx.x;
    const int b     = blockIdx.x >> 2;
    const int chunk = blockIdx.x & 3;

    #pragma unroll
    for (int i = tid; i < HSIZE; i += NT) { hkey[i] = -1; hcnt[i] = 0; }
    #pragma unroll
    for (int s = tid; s < SEQ; s += NT) tok_sh[s] = x[s * BATCH + b];
    __syncthreads();

    #pragma unroll
    for (int s = tid; s < SEQ; s += NT) {
        int tok = tok_sh[s];
        if (tok == 0) continue;
        unsigned h = hash_tok(tok);
        while (true) {
            int prev = atomicCAS(&hkey[h], -1, tok);
            if (prev == -1 || prev == tok) { atomicAdd(&hcnt[h], 1); break; }
            h = (h + 1) & HMASK;
        }
    }
    __syncthreads();

    const int base = chunk * CHUNK_S;
    for (int i = tid; i < CHUNK_S; i += NT) {
        int tok = tok_sh[base + i];
        float w = 0.0f;
        if (tok != 0) {
            unsigned h = hash_tok(tok);
            while (hkey[h] != tok) h = (h + 1) & HMASK;
            w = (float)hcnt[h] * __ldg(&idf[tok]);
        }
        w_sh[i] = w;
    }
    __syncthreads();

    const int sg = tid >> 6;
    const int dq = tid & 63;
    const float4* emb4 = reinterpret_cast<const float4*>(emb);

    float4 acc0 = make_float4(0.f, 0.f, 0.f, 0.f);
    float4 acc1 = make_float4(0.f, 0.f, 0.f, 0.f);
    #pragma unroll 4
    for (int s = sg; s < CHUNK_S / 2; s += 4) {
        int   tokA = tok_sh[base + s];
        int   tokB = tok_sh[base + s + CHUNK_S / 2];
        float wA   = w_sh[s];
        float wB   = w_sh[s + CHUNK_S / 2];
        float4 vA  = __ldg(emb4 + (size_t)tokA * (D / 4) + dq);
        float4 vB  = __ldg(emb4 + (size_t)tokB * (D / 4) + dq);
        acc0.x += wA * vA.x;  acc0.y += wA * vA.y;
        acc0.z += wA * vA.z;  acc0.w += wA * vA.w;
        acc1.x += wB * vB.x;  acc1.y += wB * vB.y;
        acc1.z += wB * vB.z;  acc1.w += wB * vB.w;
    }
    acc0.x += acc1.x; acc0.y += acc1.y; acc0.z += acc1.z; acc0.w += acc1.w;
    red4[sg][dq] = acc0;
    __syncthreads();

    if (tid < D / 4) {
        float4 a = red4[0][tid];
        float4 c = red4[1][tid];
        float4 e = red4[2][tid];
        float4 f = red4[3][tid];
        float4 r = make_float4(a.x + c.x + e.x + f.x,
                               a.y + c.y + e.y + f.y,
                               a.z + c.z + e.z + f.z,
                               a.w + c.w + e.w + f.w);
        reinterpret_cast<float4*>(g_partial + ((size_t)b * CHUNKS + chunk) * D)[tid] = r;
    }
}

// ---------------------------------------------------------------------------
// Kernel 2: per-batch MLP, 64 CTAs x 1024 threads. Weights+biases staged to
// smem; dot products split 4-ways per thread-quad + shfl combine.
// Shfl participation is WARP-ALIGNED (guards rounded up to 32) — the R9
// deadlock fix; only the smem writes are guarded by j < H1/H2.
// ---------------------------------------------------------------------------
__global__ __launch_bounds__(MT, 1)
void mlp_kernel(const float* __restrict__ W1, const float* __restrict__ b1,
                const float* __restrict__ W2, const float* __restrict__ b2,
                const float* __restrict__ W3, const float* __restrict__ b3,
                float* __restrict__ out) {
    extern __shared__ float sm[];
    float* w1s = sm + OFF_W1;
    float* w2s = sm + OFF_W2;
    float* w3s = sm + OFF_W3;
    float* pls = sm + OFF_PL;
    float* h1s = sm + OFF_H1;
    float* h2s = sm + OFF_H2;
    float* b1s = sm + OFF_B1;
    float* b2s = sm + OFF_B2;
    float* b3s = sm + OFF_B3;
    float* zs  = sm + OFF_Z;

    const int tid = threadIdx.x;
    const int b   = blockIdx.x;

    // partial reduce -> pooled (threads 0-255)
    if (tid < D) {
        const float* p = g_partial + (size_t)b * CHUNKS * D;
        pls[tid] = __ldcg(p + tid) + __ldcg(p + D + tid) +
                   __ldcg(p + 2 * D + tid) + __ldcg(p + 3 * D + tid);
    }

    // stage W1 [100 x 256] -> stride 257
    const float4* W1v = reinterpret_cast<const float4*>(W1);
    for (int f = tid; f < H1 * (D / 4); f += MT) {
        int j  = f >> 6;
        int dq = f & 63;
        float4 v = __ldg(W1v + f);
        float* dst = w1s + j * W1_STRIDE + dq * 4;
        dst[0] = v.x; dst[1] = v.y; dst[2] = v.z; dst[3] = v.w;
    }
    // stage W2 [150 x 100] -> stride 101
    const float4* W2v = reinterpret_cast<const float4*>(W2);
    for (int f = tid; f < H2 * (H1 / 4); f += MT) {
        int j  = f / 25;
        int dq = f % 25;
        float4 v = __ldg(W2v + f);
        float* dst = w2s + j * W2_STRIDE + dq * 4;
        dst[0] = v.x; dst[1] = v.y; dst[2] = v.z; dst[3] = v.w;
    }
    // stage W3 + biases
    const float4* W3v = reinterpret_cast<const float4*>(W3);
    if (tid < 75) {
        float4 v = __ldg(W3v + tid);
        float* dst = w3s + tid * 4;
        dst[0] = v.x; dst[1] = v.y; dst[2] = v.z; dst[3] = v.w;
    }
    if (tid >= 128 && tid < 128 + H1) b1s[tid - 128] = __ldg(b1 + (tid - 128));
    if (tid >= 256 && tid < 256 + H2) b2s[tid - 256] = __ldg(b2 + (tid - 256));
    if (tid >= 448 && tid < 450)      b3s[tid - 448] = __ldg(b3 + (tid - 448));
    __syncthreads();

    // L1: quad per output. Warp-aligned participation: tids [0, 416).
    // j in [0, 104); rows 100-103 read in-bounds garbage (w2s region);
    // only j < 100 writes.
    if (tid < 416) {
        const int j = tid >> 2;
        const int s = tid & 3;
        const float* w = w1s + j * W1_STRIDE;
        float a = 0.f;
        #pragma unroll 16
        for (int i = 0; i < D / 4; i++) {
            int d = 4 * i + s;
            a += pls[d] * w[d];
        }
        a += __shfl_xor_sync(0xffffffffu, a, 1);
        a += __shfl_xor_sync(0xffffffffu, a, 2);
        if (s == 0 && j < H1) h1s[j] = fmaxf(a + b1s[j], 0.f);
    }
    __syncthreads();

    // L2: quad per output. Warp-aligned: tids [0, 608), j in [0, 152).
    if (tid < 608) {
        const int j = tid >> 2;
        const int s = tid & 3;
        const float* w = w2s + j * W2_STRIDE;
        float a = 0.f;
        #pragma unroll
        for (int i = 0; i < H1 / 4; i++) {
            int d = 4 * i + s;
            a += h1s[d] * w[d];
        }
        a += __shfl_xor_sync(0xffffffffu, a, 1);
        a += __shfl_xor_sync(0xffffffffu, a, 2);
        if (s == 0 && j < H2) h2s[j] = fmaxf(a + b2s[j], 0.f);
    }
    __syncthreads();

    // L3: warp per logit (threads 0-63, two full warps), shfl reduce.
    if (tid < 64) {
        const int o    = tid >> 5;
        const int lane = tid & 31;
        const float* w = w3s + o * H2;
        float a = 0.f;
        for (int d = lane; d < H2; d += 32) a += h2s[d] * w[d];
        #pragma unroll
        for (int off = 16; off; off >>= 1) a += __shfl_xor_sync(0xffffffffu, a, off);
        if (lane == 0) zs[o] = a + b3s[o];
    }
    __syncthreads();

    if (tid == 0) {
        float z0 = zs[0], z1 = zs[1];
        float m  = fmaxf(z0, z1);
        float e0 = expf(z0 - m);
        float e1 = expf(z1 - m);
        float inv = 1.0f / (e0 + e1);
        out[b * 2 + 0] = e0 * inv;
        out[b * 2 + 1] = e1 * inv;
    }
}

extern "C" void kernel_launch(void* const* d_in, const int* in_sizes, int n_in,
                              void* d_out, int out_size) {
    const int*   x   = (const int*)  d_in[0];
    const float* emb = (const float*)d_in[1];
    const float* idf = (const float*)d_in[2];
    const float* W1  = (const float*)d_in[3];
    const float* b1  = (const float*)d_in[4];
    const float* W2  = (const float*)d_in[5];
    const float* b2  = (const float*)d_in[6];
    const float* W3  = (const float*)d_in[7];
    const float* b3  = (const float*)d_in[8];
    float* out = (float*)d_out;

    static int smem_set = 0;
    if (!smem_set) {
        cudaFuncSetAttribute(mlp_kernel,
                             cudaFuncAttributeMaxDynamicSharedMemorySize,
                             MLP_SMEM_BYTES);
        smem_set = 1;
    }

    pool_kernel<<<BATCH * CHUNKS, NT>>>(x, emb, idf);
    mlp_kernel<<<BATCH, MT, MLP_SMEM_BYTES>>>(W1, b1, W2, b2, W3, b3, out);
}